// round 2
// baseline (speedup 1.0000x reference)
#include <cuda_runtime.h>

// ---------------- problem constants (fixed by the dataset) ----------------
constexpr int NN   = 50000;   // nodes
constexpr int EE   = 800000;  // edges
constexpr int GG   = 256;     // graphs
constexpr int DIN_ = 126;     // input feature dim
constexpr int HH   = 128;     // hidden dim
constexpr int NCHUNK = (NN + 1023) / 1024;  // scan chunks

// ---------------- device scratch (static globals; no allocation) ----------
__device__ float g_x[NN * HH];          // padded input (126 -> 128)
__device__ float g_h1[NN * HH];         // hidden ping
__device__ float g_h2[NN * HH];         // hidden pong
__device__ float g_kqvs[4 * NN * HH];   // K,Q,V,S planes
__device__ float g_Wp[12 * HH * HH];    // padded weights: [layer][K,Q,V,S][128][128]
__device__ float g_bp[12 * HH];         // biases
__device__ int   g_src[EE];
__device__ int   g_dst[EE];
__device__ int   g_ssort[EE];           // src ids sorted by dst (CSR payload)
__device__ int   g_batch[NN];
__device__ int   g_cnt[NN];
__device__ int   g_incl[NN];
__device__ int   g_cursor[NN];
__device__ int   g_rowptr[NN + 1];
__device__ int   g_bsum[NCHUNK];
__device__ int   g_boff[NCHUNK];
__device__ float g_hg[GG * HH];
__device__ int   g_flag_ei64;           // 1 if edge_index is int64
__device__ int   g_flag_bt64;           // 1 if batch is int64

// ---------------- fast sigmoid: FFMA/ALU only, no MUFU --------------------
// sigmoid(x) = 1 / (1 + 2^(-x*log2(e)))
// exp2 via round-to-int magic + degree-6 poly + exponent-bit insert (~1e-7).
// reciprocal via bit-trick initial guess + 3 Newton iterations (~1e-11 rel).
__device__ __forceinline__ float fast_sigmoid(float x) {
    float t = -1.4426950408889634f * x;
    t = fminf(64.0f, fmaxf(-64.0f, t));
    float z = t + 12582912.0f;                    // round-to-nearest-int trick (1.5*2^23)
    int   ii = __float_as_int(z) - 0x4B400000;    // integer part
    float f  = t - (z - 12582912.0f);             // frac in [-0.5, 0.5]
    float p = 1.5403530393e-4f;
    p = fmaf(p, f, 1.3333558146e-3f);
    p = fmaf(p, f, 9.6181291076e-3f);
    p = fmaf(p, f, 5.5504108664e-2f);
    p = fmaf(p, f, 2.4022650696e-1f);
    p = fmaf(p, f, 6.9314718056e-1f);
    p = fmaf(p, f, 1.0f);
    float e = __int_as_float(__float_as_int(p) + (ii << 23));  // p * 2^ii
    float a = 1.0f + e;
    float r = __int_as_float(0x7EF311C3 - __float_as_int(a));  // ~1/a
    r = r * fmaf(-a, r, 2.0f);
    r = r * fmaf(-a, r, 2.0f);
    r = r * fmaf(-a, r, 2.0f);
    return r;
}

// ---------------- dtype detection (int32 vs int64 index buffers) -----------
// int64 little-endian: every odd 32-bit word is a zero high-word (values < 2^31).
// edge_index: probe odd words near the start (random ids, ~never all zero if int32).
// batch: sorted ascending from 0, so probe odd words near the END (ids ~255 if int32).
__global__ void k_detect(const int* __restrict__ ei32, const int* __restrict__ bt32) {
    if (blockIdx.x == 0 && threadIdx.x == 0) {
        int z = 1;
        for (int i = 1; i < 64; i += 2) if (ei32[i] != 0) z = 0;
        g_flag_ei64 = z;
        int z2 = 1;
        for (int i = NN - 15; i < NN; i += 2) if (bt32[i] != 0) z2 = 0;  // odd indices
        g_flag_bt64 = z2;
    }
}

// ---------------- prep kernels --------------------------------------------
__global__ void k_prep_idx(const void* __restrict__ ei) {
    int e = blockIdx.x * blockDim.x + threadIdx.x;
    if (e >= EE) return;
    int s, d;
    if (g_flag_ei64) {
        const long long* p = (const long long*)ei;
        s = (int)p[e];
        d = (int)p[EE + e];
    } else {
        const int* p = (const int*)ei;
        s = p[e];
        d = p[EE + e];
    }
    if ((unsigned)s >= (unsigned)NN) s = 0;   // defensive clamp
    if ((unsigned)d >= (unsigned)NN) d = 0;
    g_src[e] = s;
    g_dst[e] = d;
}

__global__ void k_prep_batch(const void* __restrict__ b) {
    int n = blockIdx.x * blockDim.x + threadIdx.x;
    if (n >= NN) return;
    int v;
    if (g_flag_bt64) v = (int)((const long long*)b)[n];
    else             v = ((const int*)b)[n];
    if ((unsigned)v >= (unsigned)GG) v = 0;
    g_batch[n] = v;
    g_cnt[n]   = 0;
}

__global__ void k_prep_x(const float* __restrict__ x) {
    int i = blockIdx.x * blockDim.x + threadIdx.x;
    if (i >= NN * HH) return;
    int n = i >> 7, c = i & 127;
    g_x[i] = (c < DIN_) ? x[n * DIN_ + c] : 0.0f;
}

// pad/copy one weight [D,128] -> [128,128] (zero rows >= D) and its bias
__global__ void k_prep_w(const float* __restrict__ W, const float* __restrict__ b,
                         int slot, int D) {
    int i = blockIdx.x * blockDim.x + threadIdx.x;
    if (i < HH * HH) {
        int r = i >> 7;
        g_Wp[slot * HH * HH + i] = (r < D) ? W[i] : 0.0f;  // src row-major [D,128]
    } else if (i < HH * HH + HH) {
        int c = i - HH * HH;
        g_bp[slot * HH + c] = b[c];
    }
}

// ---------------- CSR build: histogram, 2-level scan, scatter --------------
__global__ void k_count() {
    int e = blockIdx.x * blockDim.x + threadIdx.x;
    if (e >= EE) return;
    atomicAdd(&g_cnt[g_dst[e]], 1);
}

__global__ void k_scan1() {   // per-1024-chunk inclusive scan
    __shared__ int s[1024];
    int t = threadIdx.x;
    int i = blockIdx.x * 1024 + t;
    int v = (i < NN) ? g_cnt[i] : 0;
    s[t] = v;
    __syncthreads();
    #pragma unroll
    for (int off = 1; off < 1024; off <<= 1) {
        int u = (t >= off) ? s[t - off] : 0;
        __syncthreads();
        s[t] += u;
        __syncthreads();
    }
    if (i < NN) g_incl[i] = s[t];
    if (t == 1023) g_bsum[blockIdx.x] = s[t];
}

__global__ void k_scan2() {   // scan chunk totals (tiny)
    if (threadIdx.x == 0) {
        int run = 0;
        for (int b = 0; b < NCHUNK; b++) { g_boff[b] = run; run += g_bsum[b]; }
    }
}

__global__ void k_scan3() {   // finalize rowptr + cursors
    int i = blockIdx.x * blockDim.x + threadIdx.x;
    if (i >= NN) return;
    int incl = g_incl[i] + g_boff[i >> 10];
    g_rowptr[i + 1] = incl;
    g_cursor[i]     = incl - g_cnt[i];
    if (i == 0) g_rowptr[0] = 0;
}

__global__ void k_scatter() {
    int e = blockIdx.x * blockDim.x + threadIdx.x;
    if (e >= EE) return;
    int d = g_dst[e];
    int p = atomicAdd(&g_cursor[d], 1);
    g_ssort[p] = g_src[e];
}

// ---------------- fused KQVS GEMM: [N,128] @ [128,128] x 4 planes ---------
// grid (4, ceil(N/128)); 256 threads; 128x128 block tile, 8x8 thread tile.
__global__ void __launch_bounds__(256) k_gemm(int layer, int insel) {
    const float* __restrict__ A = (insel == 0) ? g_x : ((insel == 1) ? g_h1 : g_h2);
    __shared__ float As[16][128];   // [k][m]
    __shared__ float Bs[16][128];   // [k][n]
    int plane = blockIdx.x;
    int slot  = layer * 4 + plane;
    const float* __restrict__ W    = g_Wp + slot * HH * HH;
    const float* __restrict__ bias = g_bp + slot * HH;
    float* __restrict__ out = g_kqvs + plane * (NN * HH);

    int tid  = threadIdx.x;
    int row0 = blockIdx.y * 128;
    int tr = (tid >> 4) << 3;     // 0..120
    int tc = (tid & 15) << 3;     // 0..120

    float acc[8][8];
    #pragma unroll
    for (int i = 0; i < 8; i++)
        #pragma unroll
        for (int j = 0; j < 8; j++) acc[i][j] = 0.0f;

    int arow = tid >> 2;          // 0..63
    int acol = (tid & 3) << 2;    // 0,4,8,12
    int brow = tid >> 5;          // 0..7
    int bcol = (tid & 31) << 2;   // 0..124

    for (int k0 = 0; k0 < 128; k0 += 16) {
        #pragma unroll
        for (int h = 0; h < 2; h++) {
            int r = row0 + arow + h * 64;
            float4 v = make_float4(0.f, 0.f, 0.f, 0.f);
            if (r < NN) v = *reinterpret_cast<const float4*>(A + r * HH + k0 + acol);
            As[acol + 0][arow + h * 64] = v.x;
            As[acol + 1][arow + h * 64] = v.y;
            As[acol + 2][arow + h * 64] = v.z;
            As[acol + 3][arow + h * 64] = v.w;
        }
        #pragma unroll
        for (int h = 0; h < 2; h++) {
            *reinterpret_cast<float4*>(&Bs[brow + h * 8][bcol]) =
                *reinterpret_cast<const float4*>(W + (k0 + brow + h * 8) * HH + bcol);
        }
        __syncthreads();
        #pragma unroll
        for (int k = 0; k < 16; k++) {
            float a[8], b[8];
            *reinterpret_cast<float4*>(&a[0]) = *reinterpret_cast<const float4*>(&As[k][tr]);
            *reinterpret_cast<float4*>(&a[4]) = *reinterpret_cast<const float4*>(&As[k][tr + 4]);
            *reinterpret_cast<float4*>(&b[0]) = *reinterpret_cast<const float4*>(&Bs[k][tc]);
            *reinterpret_cast<float4*>(&b[4]) = *reinterpret_cast<const float4*>(&Bs[k][tc + 4]);
            #pragma unroll
            for (int i = 0; i < 8; i++)
                #pragma unroll
                for (int j = 0; j < 8; j++)
                    acc[i][j] = fmaf(a[i], b[j], acc[i][j]);
        }
        __syncthreads();
    }

    float bv[8];
    #pragma unroll
    for (int j = 0; j < 8; j++) bv[j] = bias[tc + j];
    #pragma unroll
    for (int i = 0; i < 8; i++) {
        int r = row0 + tr + i;
        if (r < NN) {
            float4 o0 = make_float4(acc[i][0] + bv[0], acc[i][1] + bv[1],
                                    acc[i][2] + bv[2], acc[i][3] + bv[3]);
            float4 o1 = make_float4(acc[i][4] + bv[4], acc[i][5] + bv[5],
                                    acc[i][6] + bv[6], acc[i][7] + bv[7]);
            *reinterpret_cast<float4*>(out + r * HH + tc)     = o0;
            *reinterpret_cast<float4*>(out + r * HH + tc + 4) = o1;
        }
    }
}

// ---------------- edge aggregation: warp per dst node, no atomics ----------
__global__ void k_edge(int outsel, int relu) {
    float* __restrict__ hout = (outsel == 1) ? g_h1 : g_h2;
    int gt = blockIdx.x * blockDim.x + threadIdx.x;
    int n = gt >> 5;
    if (n >= NN) return;
    int lane = gt & 31;

    const float4* __restrict__ K4 = reinterpret_cast<const float4*>(g_kqvs);
    const float4* __restrict__ Q4 = K4 + NN * 32;
    const float4* __restrict__ V4 = Q4 + NN * 32;
    const float4* __restrict__ S4 = V4 + NN * 32;

    float4 k4  = K4[n * 32 + lane];
    float4 acc = make_float4(0.f, 0.f, 0.f, 0.f);

    int beg = g_rowptr[n], end = g_rowptr[n + 1];
    for (int j = beg; j < end; j += 32) {
        int m = end - j; if (m > 32) m = 32;
        int sreg = (lane < m) ? g_ssort[j + lane] : 0;
        for (int t = 0; t < m; t++) {
            int s = __shfl_sync(0xffffffffu, sreg, t);
            float4 q4 = Q4[s * 32 + lane];
            float4 v4 = V4[s * 32 + lane];
            acc.x = fmaf(fast_sigmoid(k4.x + q4.x), v4.x, acc.x);
            acc.y = fmaf(fast_sigmoid(k4.y + q4.y), v4.y, acc.y);
            acc.z = fmaf(fast_sigmoid(k4.z + q4.z), v4.z, acc.z);
            acc.w = fmaf(fast_sigmoid(k4.w + q4.w), v4.w, acc.w);
        }
    }
    float4 s4 = S4[n * 32 + lane];
    float4 o = make_float4(acc.x + s4.x, acc.y + s4.y, acc.z + s4.z, acc.w + s4.w);
    if (relu) {
        o.x = fmaxf(o.x, 0.f); o.y = fmaxf(o.y, 0.f);
        o.z = fmaxf(o.z, 0.f); o.w = fmaxf(o.w, 0.f);
    }
    reinterpret_cast<float4*>(hout)[n * 32 + lane] = o;
}

// ---------------- global add pool + head MLP -------------------------------
__global__ void k_zero_hg() {
    int i = blockIdx.x * blockDim.x + threadIdx.x;
    if (i < GG * HH) g_hg[i] = 0.0f;
}

__global__ void k_pool() {
    int gt = blockIdx.x * blockDim.x + threadIdx.x;
    int n = gt >> 5;
    if (n >= NN) return;
    int lane = gt & 31;
    float4 v = reinterpret_cast<const float4*>(g_h1)[n * 32 + lane];
    int g = g_batch[n];
    float* dst = g_hg + g * HH + lane * 4;
    atomicAdd(dst + 0, v.x);
    atomicAdd(dst + 1, v.y);
    atomicAdd(dst + 2, v.z);
    atomicAdd(dst + 3, v.w);
}

__global__ void k_mlp(const float* __restrict__ W4, const float* __restrict__ b4,
                      const float* __restrict__ W5, const float* __restrict__ b5,
                      float* __restrict__ out) {
    __shared__ float sh[HH];
    __shared__ float red[2];
    int g = blockIdx.x;
    int t = threadIdx.x;  // 64 threads
    sh[t]      = g_hg[g * HH + t];
    sh[t + 64] = g_hg[g * HH + t + 64];
    __syncthreads();
    float d = b4[t];
    #pragma unroll 8
    for (int k = 0; k < HH; k++) d = fmaf(sh[k], W4[k * 64 + t], d);
    float v = fmaxf(d, 0.0f) * W5[t];
    #pragma unroll
    for (int off = 16; off; off >>= 1) v += __shfl_down_sync(0xffffffffu, v, off);
    if ((t & 31) == 0) red[t >> 5] = v;
    __syncthreads();
    if (t == 0) {
        float z = red[0] + red[1] + b5[0];
        out[g] = 1.0f / (1.0f + expf(-z));
    }
}

// ---------------- launch ----------------------------------------------------
extern "C" void kernel_launch(void* const* d_in, const int* in_sizes, int n_in,
                              void* d_out, int out_size) {
    const float* x  = (const float*)d_in[0];
    const void*  ei = d_in[30];
    const void*  bt = d_in[31];
    const float* W4 = (const float*)d_in[26];
    const float* b4 = (const float*)d_in[27];
    const float* W5 = (const float*)d_in[28];
    const float* b5 = (const float*)d_in[29];

    // dtype detection then prep
    k_detect    <<<1, 32>>>((const int*)ei, (const int*)bt);
    k_prep_idx  <<<(EE + 255) / 256, 256>>>(ei);
    k_prep_batch<<<(NN + 255) / 256, 256>>>(bt);
    k_prep_x    <<<(NN * HH + 255) / 256, 256>>>(x);
    for (int l = 0; l < 3; l++) {
        for (int g = 0; g < 4; g++) {
            int slot = l * 4 + g;
            const float* W = (const float*)d_in[2 + l * 8 + g * 2];
            const float* b = (const float*)d_in[3 + l * 8 + g * 2];
            int D = (l == 0) ? DIN_ : HH;
            k_prep_w<<<(HH * HH + HH + 255) / 256, 256>>>(W, b, slot, D);
        }
    }

    // CSR build (by dst)
    k_count  <<<(EE + 255) / 256, 256>>>();
    k_scan1  <<<NCHUNK, 1024>>>();
    k_scan2  <<<1, 32>>>();
    k_scan3  <<<(NN + 255) / 256, 256>>>();
    k_scatter<<<(EE + 255) / 256, 256>>>();

    dim3 ggrid(4, (NN + 127) / 128);
    int edge_threads = NN * 32;
    int edge_blocks  = (edge_threads + 255) / 256;

    // layer 1: g_x -> g_h1
    k_gemm<<<ggrid, 256>>>(0, 0);
    k_edge<<<edge_blocks, 256>>>(1, 1);
    // layer 2: g_h1 -> g_h2
    k_gemm<<<ggrid, 256>>>(1, 1);
    k_edge<<<edge_blocks, 256>>>(2, 1);
    // layer 3: g_h2 -> g_h1 (no relu)
    k_gemm<<<ggrid, 256>>>(2, 2);
    k_edge<<<edge_blocks, 256>>>(1, 0);

    // pool + head
    k_zero_hg<<<(GG * HH + 255) / 256, 256>>>();
    k_pool   <<<edge_blocks, 256>>>();
    k_mlp    <<<GG, 64>>>(W4, b4, W5, b5, (float*)d_out);
}

// round 3
// speedup vs baseline: 1.0150x; 1.0150x over previous
#include <cuda_runtime.h>

// ---------------- problem constants (fixed by the dataset) ----------------
constexpr int NN   = 50000;   // nodes
constexpr int EE   = 800000;  // edges
constexpr int GG   = 256;     // graphs
constexpr int DIN_ = 126;     // input feature dim
constexpr int HH   = 128;     // hidden dim
constexpr int NCHUNK = (NN + 1023) / 1024;  // scan chunks

// ---------------- device scratch (static globals; no allocation) ----------
__device__ float g_x[NN * HH];          // padded input (126 -> 128)
__device__ float g_h1[NN * HH];         // hidden ping
__device__ float g_h2[NN * HH];         // hidden pong
__device__ float g_kqvs[4 * NN * HH];   // K,Q,V,S planes
__device__ float g_Wp[12 * HH * HH];    // padded weights: [layer][K,Q,V,S][128][128]
__device__ float g_bp[12 * HH];         // biases
__device__ int   g_src[EE];
__device__ int   g_dst[EE];
__device__ int   g_ssort[EE];           // src ids sorted by dst (CSR payload)
__device__ int   g_batch[NN];
__device__ int   g_cnt[NN];
__device__ int   g_incl[NN];
__device__ int   g_cursor[NN];
__device__ int   g_rowptr[NN + 1];
__device__ int   g_bsum[NCHUNK];
__device__ int   g_boff[NCHUNK];
__device__ float g_hg[GG * HH];
__device__ int   g_flag_ei64;           // 1 if edge_index is int64
__device__ int   g_flag_bt64;           // 1 if batch is int64

// ---------------- packed f32x2 helpers (Blackwell FFMA2 path) --------------
__device__ __forceinline__ unsigned long long pack_dup(float v) {
    unsigned long long r;
    asm("mov.b64 %0, {%1, %1};" : "=l"(r) : "f"(v));
    return r;
}
__device__ __forceinline__ void fma2(unsigned long long& d, unsigned long long a,
                                     unsigned long long b) {
    asm("fma.rn.f32x2 %0, %1, %2, %0;" : "+l"(d) : "l"(a), "l"(b));
}
__device__ __forceinline__ void unpack2(unsigned long long v, float& lo, float& hi) {
    asm("mov.b64 {%0, %1}, %2;" : "=f"(lo), "=f"(hi) : "l"(v));
}

// ---------------- fast sigmoid: FFMA/ALU only, no MUFU --------------------
__device__ __forceinline__ float fast_sigmoid(float x) {
    float t = -1.4426950408889634f * x;
    t = fminf(64.0f, fmaxf(-64.0f, t));
    float z = t + 12582912.0f;                    // round-to-nearest-int trick (1.5*2^23)
    int   ii = __float_as_int(z) - 0x4B400000;    // integer part
    float f  = t - (z - 12582912.0f);             // frac in [-0.5, 0.5]
    float p = 1.5403530393e-4f;
    p = fmaf(p, f, 1.3333558146e-3f);
    p = fmaf(p, f, 9.6181291076e-3f);
    p = fmaf(p, f, 5.5504108664e-2f);
    p = fmaf(p, f, 2.4022650696e-1f);
    p = fmaf(p, f, 6.9314718056e-1f);
    p = fmaf(p, f, 1.0f);
    float e = __int_as_float(__float_as_int(p) + (ii << 23));  // p * 2^ii
    float a = 1.0f + e;
    float r = __int_as_float(0x7EF311C3 - __float_as_int(a));  // ~1/a
    r = r * fmaf(-a, r, 2.0f);
    r = r * fmaf(-a, r, 2.0f);
    r = r * fmaf(-a, r, 2.0f);
    return r;
}

// ---------------- dtype detection (int32 vs int64 index buffers) -----------
__global__ void k_detect(const int* __restrict__ ei32, const int* __restrict__ bt32) {
    if (blockIdx.x == 0 && threadIdx.x == 0) {
        int z = 1;
        for (int i = 1; i < 64; i += 2) if (ei32[i] != 0) z = 0;
        g_flag_ei64 = z;
        int z2 = 1;
        for (int i = NN - 15; i < NN; i += 2) if (bt32[i] != 0) z2 = 0;  // odd indices
        g_flag_bt64 = z2;
    }
}

// ---------------- prep kernels --------------------------------------------
__global__ void k_prep_idx(const void* __restrict__ ei) {
    int e = blockIdx.x * blockDim.x + threadIdx.x;
    if (e >= EE) return;
    int s, d;
    if (g_flag_ei64) {
        const long long* p = (const long long*)ei;
        s = (int)p[e];
        d = (int)p[EE + e];
    } else {
        const int* p = (const int*)ei;
        s = p[e];
        d = p[EE + e];
    }
    if ((unsigned)s >= (unsigned)NN) s = 0;   // defensive clamp
    if ((unsigned)d >= (unsigned)NN) d = 0;
    g_src[e] = s;
    g_dst[e] = d;
}

__global__ void k_prep_batch(const void* __restrict__ b) {
    int n = blockIdx.x * blockDim.x + threadIdx.x;
    if (n >= NN) return;
    int v;
    if (g_flag_bt64) v = (int)((const long long*)b)[n];
    else             v = ((const int*)b)[n];
    if ((unsigned)v >= (unsigned)GG) v = 0;
    g_batch[n] = v;
    g_cnt[n]   = 0;
}

__global__ void k_prep_x(const float* __restrict__ x) {
    int i = blockIdx.x * blockDim.x + threadIdx.x;
    if (i >= NN * HH) return;
    int n = i >> 7, c = i & 127;
    g_x[i] = (c < DIN_) ? x[n * DIN_ + c] : 0.0f;
}

// pad/copy one weight [D,128] -> [128,128] (zero rows >= D) and its bias
__global__ void k_prep_w(const float* __restrict__ W, const float* __restrict__ b,
                         int slot, int D) {
    int i = blockIdx.x * blockDim.x + threadIdx.x;
    if (i < HH * HH) {
        int r = i >> 7;
        g_Wp[slot * HH * HH + i] = (r < D) ? W[i] : 0.0f;  // src row-major [D,128]
    } else if (i < HH * HH + HH) {
        int c = i - HH * HH;
        g_bp[slot * HH + c] = b[c];
    }
}

// ---------------- CSR build: histogram, 2-level scan, scatter --------------
__global__ void k_count() {
    int e = blockIdx.x * blockDim.x + threadIdx.x;
    if (e >= EE) return;
    atomicAdd(&g_cnt[g_dst[e]], 1);
}

__global__ void k_scan1() {   // per-1024-chunk inclusive scan
    __shared__ int s[1024];
    int t = threadIdx.x;
    int i = blockIdx.x * 1024 + t;
    int v = (i < NN) ? g_cnt[i] : 0;
    s[t] = v;
    __syncthreads();
    #pragma unroll
    for (int off = 1; off < 1024; off <<= 1) {
        int u = (t >= off) ? s[t - off] : 0;
        __syncthreads();
        s[t] += u;
        __syncthreads();
    }
    if (i < NN) g_incl[i] = s[t];
    if (t == 1023) g_bsum[blockIdx.x] = s[t];
}

__global__ void k_scan2() {   // scan chunk totals (tiny)
    if (threadIdx.x == 0) {
        int run = 0;
        for (int b = 0; b < NCHUNK; b++) { g_boff[b] = run; run += g_bsum[b]; }
    }
}

__global__ void k_scan3() {   // finalize rowptr + cursors
    int i = blockIdx.x * blockDim.x + threadIdx.x;
    if (i >= NN) return;
    int incl = g_incl[i] + g_boff[i >> 10];
    g_rowptr[i + 1] = incl;
    g_cursor[i]     = incl - g_cnt[i];
    if (i == 0) g_rowptr[0] = 0;
}

__global__ void k_scatter() {
    int e = blockIdx.x * blockDim.x + threadIdx.x;
    if (e >= EE) return;
    int d = g_dst[e];
    int p = atomicAdd(&g_cursor[d], 1);
    g_ssort[p] = g_src[e];
}

// ---------------- fused KQVS GEMM: [N,128] @ [128,128] x 4 planes ---------
// grid (4, ceil(N/128)); 256 threads; 128x128 block tile, 8x8 thread tile.
// Inner product uses Blackwell packed fma.rn.f32x2 (2 FMA per issue).
__global__ void __launch_bounds__(256) k_gemm(int layer, int insel) {
    const float* __restrict__ A = (insel == 0) ? g_x : ((insel == 1) ? g_h1 : g_h2);
    __shared__ float As[16][128];   // [k][m]
    __shared__ float Bs[16][128];   // [k][n]
    int plane = blockIdx.x;
    int slot  = layer * 4 + plane;
    const float* __restrict__ W    = g_Wp + slot * HH * HH;
    const float* __restrict__ bias = g_bp + slot * HH;
    float* __restrict__ out = g_kqvs + plane * (NN * HH);

    int tid  = threadIdx.x;
    int row0 = blockIdx.y * 128;
    int tr = (tid >> 4) << 3;     // 0..120
    int tc = (tid & 15) << 3;     // 0..120

    unsigned long long acc2[8][4];   // 8 rows x 4 packed column-pairs
    #pragma unroll
    for (int i = 0; i < 8; i++)
        #pragma unroll
        for (int j = 0; j < 4; j++) acc2[i][j] = 0ULL;

    int arow = tid >> 2;          // 0..63
    int acol = (tid & 3) << 2;    // 0,4,8,12
    int brow = tid >> 5;          // 0..7
    int bcol = (tid & 31) << 2;   // 0..124

    for (int k0 = 0; k0 < 128; k0 += 16) {
        #pragma unroll
        for (int h = 0; h < 2; h++) {
            int r = row0 + arow + h * 64;
            float4 v = make_float4(0.f, 0.f, 0.f, 0.f);
            if (r < NN) v = *reinterpret_cast<const float4*>(A + r * HH + k0 + acol);
            As[acol + 0][arow + h * 64] = v.x;
            As[acol + 1][arow + h * 64] = v.y;
            As[acol + 2][arow + h * 64] = v.z;
            As[acol + 3][arow + h * 64] = v.w;
        }
        #pragma unroll
        for (int h = 0; h < 2; h++) {
            *reinterpret_cast<float4*>(&Bs[brow + h * 8][bcol]) =
                *reinterpret_cast<const float4*>(W + (k0 + brow + h * 8) * HH + bcol);
        }
        __syncthreads();
        #pragma unroll
        for (int k = 0; k < 16; k++) {
            float a[8];
            *reinterpret_cast<float4*>(&a[0]) = *reinterpret_cast<const float4*>(&As[k][tr]);
            *reinterpret_cast<float4*>(&a[4]) = *reinterpret_cast<const float4*>(&As[k][tr + 4]);
            unsigned long long b2[4];
            *reinterpret_cast<ulonglong2*>(&b2[0]) =
                *reinterpret_cast<const ulonglong2*>(&Bs[k][tc]);
            *reinterpret_cast<ulonglong2*>(&b2[2]) =
                *reinterpret_cast<const ulonglong2*>(&Bs[k][tc + 4]);
            #pragma unroll
            for (int i = 0; i < 8; i++) {
                unsigned long long aa = pack_dup(a[i]);
                #pragma unroll
                for (int j = 0; j < 4; j++) fma2(acc2[i][j], aa, b2[j]);
            }
        }
        __syncthreads();
    }

    float bv[8];
    #pragma unroll
    for (int j = 0; j < 8; j++) bv[j] = bias[tc + j];
    #pragma unroll
    for (int i = 0; i < 8; i++) {
        int r = row0 + tr + i;
        if (r < NN) {
            float o[8];
            #pragma unroll
            for (int j = 0; j < 4; j++) {
                float lo, hi;
                unpack2(acc2[i][j], lo, hi);
                o[2 * j]     = lo + bv[2 * j];
                o[2 * j + 1] = hi + bv[2 * j + 1];
            }
            *reinterpret_cast<float4*>(out + r * HH + tc)     =
                make_float4(o[0], o[1], o[2], o[3]);
            *reinterpret_cast<float4*>(out + r * HH + tc + 4) =
                make_float4(o[4], o[5], o[6], o[7]);
        }
    }
}

// ---------------- edge aggregation: warp per dst node, no atomics ----------
__global__ void k_edge(int outsel, int relu) {
    float* __restrict__ hout = (outsel == 1) ? g_h1 : g_h2;
    int gt = blockIdx.x * blockDim.x + threadIdx.x;
    int n = gt >> 5;
    if (n >= NN) return;
    int lane = gt & 31;

    const float4* __restrict__ K4 = reinterpret_cast<const float4*>(g_kqvs);
    const float4* __restrict__ Q4 = K4 + NN * 32;
    const float4* __restrict__ V4 = Q4 + NN * 32;
    const float4* __restrict__ S4 = V4 + NN * 32;

    float4 k4  = K4[n * 32 + lane];
    float4 acc = make_float4(0.f, 0.f, 0.f, 0.f);

    int beg = g_rowptr[n], end = g_rowptr[n + 1];
    for (int j = beg; j < end; j += 32) {
        int m = end - j; if (m > 32) m = 32;
        int sreg = (lane < m) ? g_ssort[j + lane] : 0;
        for (int t = 0; t < m; t++) {
            int s = __shfl_sync(0xffffffffu, sreg, t);
            float4 q4 = Q4[s * 32 + lane];
            float4 v4 = V4[s * 32 + lane];
            acc.x = fmaf(fast_sigmoid(k4.x + q4.x), v4.x, acc.x);
            acc.y = fmaf(fast_sigmoid(k4.y + q4.y), v4.y, acc.y);
            acc.z = fmaf(fast_sigmoid(k4.z + q4.z), v4.z, acc.z);
            acc.w = fmaf(fast_sigmoid(k4.w + q4.w), v4.w, acc.w);
        }
    }
    float4 s4 = S4[n * 32 + lane];
    float4 o = make_float4(acc.x + s4.x, acc.y + s4.y, acc.z + s4.z, acc.w + s4.w);
    if (relu) {
        o.x = fmaxf(o.x, 0.f); o.y = fmaxf(o.y, 0.f);
        o.z = fmaxf(o.z, 0.f); o.w = fmaxf(o.w, 0.f);
    }
    reinterpret_cast<float4*>(hout)[n * 32 + lane] = o;
}

// ---------------- global add pool + head MLP -------------------------------
__global__ void k_zero_hg() {
    int i = blockIdx.x * blockDim.x + threadIdx.x;
    if (i < GG * HH) g_hg[i] = 0.0f;
}

__global__ void k_pool() {
    int gt = blockIdx.x * blockDim.x + threadIdx.x;
    int n = gt >> 5;
    if (n >= NN) return;
    int lane = gt & 31;
    float4 v = reinterpret_cast<const float4*>(g_h1)[n * 32 + lane];
    int g = g_batch[n];
    float* dst = g_hg + g * HH + lane * 4;
    atomicAdd(dst + 0, v.x);
    atomicAdd(dst + 1, v.y);
    atomicAdd(dst + 2, v.z);
    atomicAdd(dst + 3, v.w);
}

__global__ void k_mlp(const float* __restrict__ W4, const float* __restrict__ b4,
                      const float* __restrict__ W5, const float* __restrict__ b5,
                      float* __restrict__ out) {
    __shared__ float sh[HH];
    __shared__ float red[2];
    int g = blockIdx.x;
    int t = threadIdx.x;  // 64 threads
    sh[t]      = g_hg[g * HH + t];
    sh[t + 64] = g_hg[g * HH + t + 64];
    __syncthreads();
    float d = b4[t];
    #pragma unroll 8
    for (int k = 0; k < HH; k++) d = fmaf(sh[k], W4[k * 64 + t], d);
    float v = fmaxf(d, 0.0f) * W5[t];
    #pragma unroll
    for (int off = 16; off; off >>= 1) v += __shfl_down_sync(0xffffffffu, v, off);
    if ((t & 31) == 0) red[t >> 5] = v;
    __syncthreads();
    if (t == 0) {
        float z = red[0] + red[1] + b5[0];
        out[g] = 1.0f / (1.0f + expf(-z));
    }
}

// ---------------- launch ----------------------------------------------------
extern "C" void kernel_launch(void* const* d_in, const int* in_sizes, int n_in,
                              void* d_out, int out_size) {
    const float* x  = (const float*)d_in[0];
    const void*  ei = d_in[30];
    const void*  bt = d_in[31];
    const float* W4 = (const float*)d_in[26];
    const float* b4 = (const float*)d_in[27];
    const float* W5 = (const float*)d_in[28];
    const float* b5 = (const float*)d_in[29];

    // dtype detection then prep
    k_detect    <<<1, 32>>>((const int*)ei, (const int*)bt);
    k_prep_idx  <<<(EE + 255) / 256, 256>>>(ei);
    k_prep_batch<<<(NN + 255) / 256, 256>>>(bt);
    k_prep_x    <<<(NN * HH + 255) / 256, 256>>>(x);
    for (int l = 0; l < 3; l++) {
        for (int g = 0; g < 4; g++) {
            int slot = l * 4 + g;
            const float* W = (const float*)d_in[2 + l * 8 + g * 2];
            const float* b = (const float*)d_in[3 + l * 8 + g * 2];
            int D = (l == 0) ? DIN_ : HH;
            k_prep_w<<<(HH * HH + HH + 255) / 256, 256>>>(W, b, slot, D);
        }
    }

    // CSR build (by dst)
    k_count  <<<(EE + 255) / 256, 256>>>();
    k_scan1  <<<NCHUNK, 1024>>>();
    k_scan2  <<<1, 32>>>();
    k_scan3  <<<(NN + 255) / 256, 256>>>();
    k_scatter<<<(EE + 255) / 256, 256>>>();

    dim3 ggrid(4, (NN + 127) / 128);
    int edge_threads = NN * 32;
    int edge_blocks  = (edge_threads + 255) / 256;

    // layer 1: g_x -> g_h1
    k_gemm<<<ggrid, 256>>>(0, 0);
    k_edge<<<edge_blocks, 256>>>(1, 1);
    // layer 2: g_h1 -> g_h2
    k_gemm<<<ggrid, 256>>>(1, 1);
    k_edge<<<edge_blocks, 256>>>(2, 1);
    // layer 3: g_h2 -> g_h1 (no relu)
    k_gemm<<<ggrid, 256>>>(2, 2);
    k_edge<<<edge_blocks, 256>>>(1, 0);

    // pool + head
    k_zero_hg<<<(GG * HH + 255) / 256, 256>>>();
    k_pool   <<<edge_blocks, 256>>>();
    k_mlp    <<<GG, 64>>>(W4, b4, W5, b5, (float*)d_out);
}

// round 4
// speedup vs baseline: 1.1816x; 1.1642x over previous
#include <cuda_runtime.h>

// ---------------- problem constants (fixed by the dataset) ----------------
constexpr int NN   = 50000;   // nodes
constexpr int EE   = 800000;  // edges
constexpr int GG   = 256;     // graphs
constexpr int DIN_ = 126;     // input feature dim
constexpr int HH   = 128;     // hidden dim
constexpr int NCHUNK = (NN + 1023) / 1024;  // scan chunks

// ---------------- device scratch (static globals; no allocation) ----------
__device__ float g_x[NN * HH];          // padded input (126 -> 128)
__device__ float g_h1[NN * HH];         // hidden ping
__device__ float g_h2[NN * HH];         // hidden pong
__device__ float g_kqvs[4 * NN * HH];   // K,Q,V,S planes
__device__ float g_Wp[12 * HH * HH];    // padded weights
__device__ float g_bp[12 * HH];         // biases
__device__ int   g_src[EE];
__device__ int   g_dst[EE];
__device__ int   g_ssort[EE];           // src ids sorted by dst (CSR payload)
__device__ int   g_batch[NN];
__device__ int   g_cnt[NN];
__device__ int   g_incl[NN];
__device__ int   g_cursor[NN];
__device__ int   g_rowptr[NN + 1];
__device__ int   g_bsum[NCHUNK];
__device__ int   g_boff[NCHUNK];
__device__ float g_hg[GG * HH];
__device__ int   g_flag_ei64;
__device__ int   g_flag_bt64;

// ---------------- packed f32x2 helpers --------------------------------------
__device__ __forceinline__ unsigned long long pack_dup(float v) {
    unsigned long long r;
    asm("mov.b64 %0, {%1, %1};" : "=l"(r) : "f"(v));
    return r;
}
__device__ __forceinline__ void fma2(unsigned long long& d, unsigned long long a,
                                     unsigned long long b) {
    asm("fma.rn.f32x2 %0, %1, %2, %0;" : "+l"(d) : "l"(a), "l"(b));
}
__device__ __forceinline__ void unpack2(unsigned long long v, float& lo, float& hi) {
    asm("mov.b64 {%0, %1}, %2;" : "=f"(lo), "=f"(hi) : "l"(v));
}

// ---------------- MUFU sigmoid: 2 MUFU + 2 FMA-pipe ops, err ~3e-7 ---------
__device__ __forceinline__ float sigmoid_mufu(float x) {
    float e;
    asm("ex2.approx.f32 %0, %1;" : "=f"(e) : "f"(x * -1.4426950408889634f));
    float r;
    asm("rcp.approx.f32 %0, %1;" : "=f"(r) : "f"(e + 1.0f));
    return r;
}

// ---------------- dtype detection (int32 vs int64 index buffers) -----------
__global__ void k_detect(const int* __restrict__ ei32, const int* __restrict__ bt32) {
    if (blockIdx.x == 0 && threadIdx.x == 0) {
        int z = 1;
        for (int i = 1; i < 64; i += 2) if (ei32[i] != 0) z = 0;
        g_flag_ei64 = z;
        int z2 = 1;
        for (int i = NN - 15; i < NN; i += 2) if (bt32[i] != 0) z2 = 0;
        g_flag_bt64 = z2;
    }
}

// ---------------- prep kernels --------------------------------------------
__global__ void k_prep_x(const float* __restrict__ x) {
    int i = blockIdx.x * blockDim.x + threadIdx.x;
    if (i >= NN * HH) return;
    int n = i >> 7, c = i & 127;
    g_x[i] = (c < DIN_) ? x[n * DIN_ + c] : 0.0f;
}

struct WPtrs { const float* W[12]; const float* b[12]; };

// all 12 weight pads in one kernel: grid (65, 12)
__global__ void k_prep_w_all(WPtrs p) {
    int slot = blockIdx.y;
    int i = blockIdx.x * blockDim.x + threadIdx.x;
    int D = (slot < 4) ? DIN_ : HH;
    if (i < HH * HH) {
        int r = i >> 7;
        g_Wp[slot * HH * HH + i] = (r < D) ? p.W[slot][i] : 0.0f;
    } else if (i < HH * HH + HH) {
        int c = i - HH * HH;
        g_bp[slot * HH + c] = p.b[slot][c];
    }
}

// batch convert + zero cnt + zero hg
__global__ void k_prep_batch(const void* __restrict__ b) {
    int n = blockIdx.x * blockDim.x + threadIdx.x;
    if (n >= NN) return;
    int v;
    if (g_flag_bt64) v = (int)((const long long*)b)[n];
    else             v = ((const int*)b)[n];
    if ((unsigned)v >= (unsigned)GG) v = 0;
    g_batch[n] = v;
    g_cnt[n]   = 0;
    if (n < GG * HH) g_hg[n] = 0.0f;
}

// edge index convert + dst histogram (cnt zeroed by k_prep_batch beforehand)
__global__ void k_prep_idx(const void* __restrict__ ei) {
    int e = blockIdx.x * blockDim.x + threadIdx.x;
    if (e >= EE) return;
    int s, d;
    if (g_flag_ei64) {
        const long long* p = (const long long*)ei;
        s = (int)p[e];
        d = (int)p[EE + e];
    } else {
        const int* p = (const int*)ei;
        s = p[e];
        d = p[EE + e];
    }
    if ((unsigned)s >= (unsigned)NN) s = 0;
    if ((unsigned)d >= (unsigned)NN) d = 0;
    g_src[e] = s;
    g_dst[e] = d;
    atomicAdd(&g_cnt[d], 1);
}

// ---------------- CSR build: 2-level scan + scatter ------------------------
__global__ void k_scan1() {
    __shared__ int s[1024];
    int t = threadIdx.x;
    int i = blockIdx.x * 1024 + t;
    int v = (i < NN) ? g_cnt[i] : 0;
    s[t] = v;
    __syncthreads();
    #pragma unroll
    for (int off = 1; off < 1024; off <<= 1) {
        int u = (t >= off) ? s[t - off] : 0;
        __syncthreads();
        s[t] += u;
        __syncthreads();
    }
    if (i < NN) g_incl[i] = s[t];
    if (t == 1023) g_bsum[blockIdx.x] = s[t];
}

__global__ void k_scan2() {
    if (threadIdx.x == 0) {
        int run = 0;
        for (int b = 0; b < NCHUNK; b++) { g_boff[b] = run; run += g_bsum[b]; }
    }
}

__global__ void k_scan3() {
    int i = blockIdx.x * blockDim.x + threadIdx.x;
    if (i >= NN) return;
    int incl = g_incl[i] + g_boff[i >> 10];
    g_rowptr[i + 1] = incl;
    g_cursor[i]     = incl - g_cnt[i];
    if (i == 0) g_rowptr[0] = 0;
}

__global__ void k_scatter() {
    int e = blockIdx.x * blockDim.x + threadIdx.x;
    if (e >= EE) return;
    int d = g_dst[e];
    int p = atomicAdd(&g_cursor[d], 1);
    g_ssort[p] = g_src[e];
}

// ---------------- fused KQVS GEMM: [N,128] @ [128,128] x 4 planes ---------
// grid (4, ceil(N/128)); 256 threads; packed fma.rn.f32x2 inner product.
__global__ void __launch_bounds__(256) k_gemm(int layer, int insel) {
    const float* __restrict__ A = (insel == 0) ? g_x : ((insel == 1) ? g_h1 : g_h2);
    __shared__ float As[16][128];
    __shared__ float Bs[16][128];
    int plane = blockIdx.x;
    int slot  = layer * 4 + plane;
    const float* __restrict__ W    = g_Wp + slot * HH * HH;
    const float* __restrict__ bias = g_bp + slot * HH;
    float* __restrict__ out = g_kqvs + plane * (NN * HH);

    int tid  = threadIdx.x;
    int row0 = blockIdx.y * 128;
    int tr = (tid >> 4) << 3;
    int tc = (tid & 15) << 3;

    unsigned long long acc2[8][4];
    #pragma unroll
    for (int i = 0; i < 8; i++)
        #pragma unroll
        for (int j = 0; j < 4; j++) acc2[i][j] = 0ULL;

    int arow = tid >> 2;
    int acol = (tid & 3) << 2;
    int brow = tid >> 5;
    int bcol = (tid & 31) << 2;

    for (int k0 = 0; k0 < 128; k0 += 16) {
        #pragma unroll
        for (int h = 0; h < 2; h++) {
            int r = row0 + arow + h * 64;
            float4 v = make_float4(0.f, 0.f, 0.f, 0.f);
            if (r < NN) v = *reinterpret_cast<const float4*>(A + r * HH + k0 + acol);
            As[acol + 0][arow + h * 64] = v.x;
            As[acol + 1][arow + h * 64] = v.y;
            As[acol + 2][arow + h * 64] = v.z;
            As[acol + 3][arow + h * 64] = v.w;
        }
        #pragma unroll
        for (int h = 0; h < 2; h++) {
            *reinterpret_cast<float4*>(&Bs[brow + h * 8][bcol]) =
                *reinterpret_cast<const float4*>(W + (k0 + brow + h * 8) * HH + bcol);
        }
        __syncthreads();
        #pragma unroll
        for (int k = 0; k < 16; k++) {
            float a[8];
            *reinterpret_cast<float4*>(&a[0]) = *reinterpret_cast<const float4*>(&As[k][tr]);
            *reinterpret_cast<float4*>(&a[4]) = *reinterpret_cast<const float4*>(&As[k][tr + 4]);
            unsigned long long b2[4];
            *reinterpret_cast<ulonglong2*>(&b2[0]) =
                *reinterpret_cast<const ulonglong2*>(&Bs[k][tc]);
            *reinterpret_cast<ulonglong2*>(&b2[2]) =
                *reinterpret_cast<const ulonglong2*>(&Bs[k][tc + 4]);
            #pragma unroll
            for (int i = 0; i < 8; i++) {
                unsigned long long aa = pack_dup(a[i]);
                #pragma unroll
                for (int j = 0; j < 4; j++) fma2(acc2[i][j], aa, b2[j]);
            }
        }
        __syncthreads();
    }

    float bv[8];
    #pragma unroll
    for (int j = 0; j < 8; j++) bv[j] = bias[tc + j];
    #pragma unroll
    for (int i = 0; i < 8; i++) {
        int r = row0 + tr + i;
        if (r < NN) {
            float o[8];
            #pragma unroll
            for (int j = 0; j < 4; j++) {
                float lo, hi;
                unpack2(acc2[i][j], lo, hi);
                o[2 * j]     = lo + bv[2 * j];
                o[2 * j + 1] = hi + bv[2 * j + 1];
            }
            *reinterpret_cast<float4*>(out + r * HH + tc)     =
                make_float4(o[0], o[1], o[2], o[3]);
            *reinterpret_cast<float4*>(out + r * HH + tc + 4) =
                make_float4(o[4], o[5], o[6], o[7]);
        }
    }
}

// ---------------- edge aggregation: warp per dst node, MUFU sigmoid --------
// mode: 0 -> write h with relu; 1 -> write h no relu; 2 -> pool directly (no h write)
__global__ void k_edge(int outsel, int mode) {
    float* __restrict__ hout = (outsel == 1) ? g_h1 : g_h2;
    int gt = blockIdx.x * blockDim.x + threadIdx.x;
    int n = gt >> 5;
    if (n >= NN) return;
    int lane = gt & 31;

    const float4* __restrict__ K4 = reinterpret_cast<const float4*>(g_kqvs);
    const float4* __restrict__ Q4 = K4 + NN * 32;
    const float4* __restrict__ V4 = Q4 + NN * 32;
    const float4* __restrict__ S4 = V4 + NN * 32;

    float4 k4  = K4[n * 32 + lane];
    float4 acc = make_float4(0.f, 0.f, 0.f, 0.f);

    int beg = g_rowptr[n], end = g_rowptr[n + 1];
    for (int j = beg; j < end; j += 32) {
        int m = end - j; if (m > 32) m = 32;
        int sreg = (lane < m) ? g_ssort[j + lane] : 0;
        for (int t = 0; t < m; t++) {
            int s = __shfl_sync(0xffffffffu, sreg, t);
            float4 q4 = Q4[s * 32 + lane];
            float4 v4 = V4[s * 32 + lane];
            acc.x = fmaf(sigmoid_mufu(k4.x + q4.x), v4.x, acc.x);
            acc.y = fmaf(sigmoid_mufu(k4.y + q4.y), v4.y, acc.y);
            acc.z = fmaf(sigmoid_mufu(k4.z + q4.z), v4.z, acc.z);
            acc.w = fmaf(sigmoid_mufu(k4.w + q4.w), v4.w, acc.w);
        }
    }
    float4 s4 = S4[n * 32 + lane];
    float4 o = make_float4(acc.x + s4.x, acc.y + s4.y, acc.z + s4.z, acc.w + s4.w);
    if (mode == 0) {
        o.x = fmaxf(o.x, 0.f); o.y = fmaxf(o.y, 0.f);
        o.z = fmaxf(o.z, 0.f); o.w = fmaxf(o.w, 0.f);
        reinterpret_cast<float4*>(hout)[n * 32 + lane] = o;
    } else if (mode == 1) {
        reinterpret_cast<float4*>(hout)[n * 32 + lane] = o;
    } else {
        // fused global_add_pool: accumulate into g_hg directly
        int g = g_batch[n];
        float* dst = g_hg + g * HH + lane * 4;
        atomicAdd(dst + 0, o.x);
        atomicAdd(dst + 1, o.y);
        atomicAdd(dst + 2, o.z);
        atomicAdd(dst + 3, o.w);
    }
}

// ---------------- head MLP -------------------------------------------------
__global__ void k_mlp(const float* __restrict__ W4, const float* __restrict__ b4,
                      const float* __restrict__ W5, const float* __restrict__ b5,
                      float* __restrict__ out) {
    __shared__ float sh[HH];
    __shared__ float red[2];
    int g = blockIdx.x;
    int t = threadIdx.x;  // 64 threads
    sh[t]      = g_hg[g * HH + t];
    sh[t + 64] = g_hg[g * HH + t + 64];
    __syncthreads();
    float d = b4[t];
    #pragma unroll 8
    for (int k = 0; k < HH; k++) d = fmaf(sh[k], W4[k * 64 + t], d);
    float v = fmaxf(d, 0.0f) * W5[t];
    #pragma unroll
    for (int off = 16; off; off >>= 1) v += __shfl_down_sync(0xffffffffu, v, off);
    if ((t & 31) == 0) red[t >> 5] = v;
    __syncthreads();
    if (t == 0) {
        float z = red[0] + red[1] + b5[0];
        out[g] = 1.0f / (1.0f + expf(-z));
    }
}

// ---------------- launch ----------------------------------------------------
extern "C" void kernel_launch(void* const* d_in, const int* in_sizes, int n_in,
                              void* d_out, int out_size) {
    const float* x  = (const float*)d_in[0];
    const void*  ei = d_in[30];
    const void*  bt = d_in[31];
    const float* W4 = (const float*)d_in[26];
    const float* b4 = (const float*)d_in[27];
    const float* W5 = (const float*)d_in[28];
    const float* b5 = (const float*)d_in[29];

    WPtrs wp;
    for (int l = 0; l < 3; l++)
        for (int g = 0; g < 4; g++) {
            wp.W[l * 4 + g] = (const float*)d_in[2 + l * 8 + g * 2];
            wp.b[l * 4 + g] = (const float*)d_in[3 + l * 8 + g * 2];
        }

    dim3 ggrid(4, (NN + 127) / 128);
    int edge_threads = NN * 32;
    int edge_blocks  = (edge_threads + 255) / 256;

    // launch order chosen so k_gemm occupies the ncu-captured slot (4th)
    k_prep_x    <<<(NN * HH + 255) / 256, 256>>>(x);                 // 1
    k_detect    <<<1, 32>>>((const int*)ei, (const int*)bt);         // 2
    k_prep_w_all<<<dim3(65, 12), 256>>>(wp);                         // 3
    k_gemm      <<<ggrid, 256>>>(0, 0);                              // 4  <- profile
    k_prep_batch<<<(NN + 255) / 256, 256>>>(bt);                     // 5
    k_prep_idx  <<<(EE + 255) / 256, 256>>>(ei);                     // 6
    k_scan1     <<<NCHUNK, 1024>>>();                                // 7
    k_scan2     <<<1, 32>>>();                                       // 8
    k_scan3     <<<(NN + 255) / 256, 256>>>();                       // 9
    k_scatter   <<<(EE + 255) / 256, 256>>>();                       // 10

    k_edge<<<edge_blocks, 256>>>(1, 0);   // layer 1 -> h1, relu     // 11
    k_gemm<<<ggrid, 256>>>(1, 1);         // layer 2 from h1         // 12
    k_edge<<<edge_blocks, 256>>>(2, 0);   // layer 2 -> h2, relu     // 13
    k_gemm<<<ggrid, 256>>>(2, 2);         // layer 3 from h2         // 14
    k_edge<<<edge_blocks, 256>>>(1, 2);   // layer 3 -> pool fused   // 15
    k_mlp <<<GG, 64>>>(W4, b4, W5, b5, (float*)d_out);               // 16
}